// round 2
// baseline (speedup 1.0000x reference)
#include <cuda_runtime.h>

#define TSZ 16
#define SRR 4
#define PD 1
#define SSN 11          // 2*(SR+PADD)+1
#define WINSZ 26        // T + 2*(SR+PADD)

// ---------------- scratch (no allocations allowed) ----------------
__device__ float g_ps1[4 * 256 * 256];
__device__ float g_pd1[4 * 256 * 256];
__device__ float g_ps2[4 * 128 * 128];
__device__ float g_pd2[4 * 128 * 128];
__device__ float g_ps3[4 * 64 * 64];
__device__ float g_pd3[4 * 64 * 64];
__device__ float g_offA[4 * 32 * 32 * 2];
__device__ float g_offB[4 * 32 * 32 * 2];

// ---------------- fused gaussian blur (5x5, zero-pad) + 2x2 avg pool ----------------
__global__ void blur_pool_kernel(const float* __restrict__ inS, const float* __restrict__ inD,
                                 float* __restrict__ outS, float* __restrict__ outD,
                                 int Hin, int Win2) {
    int Ho = Hin >> 1, Wo = Win2 >> 1;
    int ox = blockIdx.x * blockDim.x + threadIdx.x;
    int oy = blockIdx.y * blockDim.y + threadIdx.y;
    if (ox >= Wo || oy >= Ho) return;
    int z = blockIdx.z;  // 0..3 src images, 4..7 dst images
    const float* in = (z < 4 ? inS : inD) + (size_t)(z & 3) * Hin * Win2;
    float* out = (z < 4 ? outS : outD) + (size_t)(z & 3) * Ho * Wo;

    const float w0 = 0.13533528323661270f;  // exp(-2)
    const float w1 = 0.60653065971263342f;  // exp(-0.5)
    const float wv[5] = {w0, w1, 1.0f, w1, w0};
    const float ksum = 1.0f + 2.0f * w1 + 2.0f * w0;
    const float norm = 1.0f / (ksum * ksum);

    float acc = 0.0f;
    for (int py = 0; py < 2; py++) {
        for (int px = 0; px < 2; px++) {
            int cy = 2 * oy + py, cx = 2 * ox + px;
            float s = 0.0f;
            #pragma unroll
            for (int a = 0; a < 5; a++) {
                int yy = cy + a - 2;
                if (yy < 0 || yy >= Hin) continue;
                #pragma unroll
                for (int b = 0; b < 5; b++) {
                    int xx = cx + b - 2;
                    if (xx < 0 || xx >= Win2) continue;
                    s += (wv[a] * wv[b] * norm) * in[(size_t)yy * Win2 + xx];
                }
            }
            acc += s;
        }
    }
    out[(size_t)oy * Wo + ox] = acc * 0.25f;
}

// ---------------- one block-matching step; 1 CTA per tile ----------------
__global__ void __launch_bounds__(128) match_kernel(
    const float* __restrict__ src, const float* __restrict__ dst,
    int H, int W, int nth, int ntw,
    const float* __restrict__ prevOff,       // nullptr => zero init (coarsest level)
    float* __restrict__ outOff,              // per-tile offsets (nullptr at finest)
    float* __restrict__ outPixOff,           // finest level: expanded pixel offsets
    float* __restrict__ outPixDist)          // finest level: expanded min dist
{
    __shared__ float s_win[WINSZ * WINSZ];
    __shared__ float s_tile[TSZ * TSZ];
    __shared__ float s_dist[SSN * SSN];
    __shared__ float s_init[2];
    __shared__ int s_o[2];
    __shared__ float s_res[3];

    int tx = blockIdx.x, ty = blockIdx.y, n = blockIdx.z;
    int tid = threadIdx.x;

    if (tid == 0) {
        float i0 = 0.0f, i1 = 0.0f;
        if (prevOff) {
            // _inherit: parent tile offset *2, clamp tile position, round (half-even)
            int pn = nth >> 1, pw = ntw >> 1;
            const float* p = &prevOff[(((size_t)n * pn + (ty >> 1)) * pw + (tx >> 1)) * 2];
            float o0 = 2.0f * p[0], o1 = 2.0f * p[1];
            float fy = (float)(ty * TSZ), fx = (float)(tx * TSZ);
            float dy = fminf(fmaxf(o0 + fy, 0.0f), (float)(H - TSZ)) - fy;
            float dx = fminf(fmaxf(o1 + fx, 0.0f), (float)(W - TSZ)) - fx;
            i0 = rintf(dy);
            i1 = rintf(dx);
        }
        s_init[0] = i0; s_init[1] = i1;
        s_o[0] = (int)i0; s_o[1] = (int)i1;  // already integral
    }
    __syncthreads();

    int y0 = ty * TSZ + s_o[0] - (SRR + PD);
    int x0 = tx * TSZ + s_o[1] - (SRR + PD);
    const float* dbase = dst + (size_t)n * H * W;
    const float* sbase = src + (size_t)n * H * W;

    // gather 26x26 window from dst with clamped indices
    for (int i = tid; i < WINSZ * WINSZ; i += 128) {
        int wy = i / WINSZ, wx = i % WINSZ;
        int gy = min(max(y0 + wy, 0), H - 1);
        int gx = min(max(x0 + wx, 0), W - 1);
        s_win[i] = dbase[(size_t)gy * W + gx];
    }
    // 16x16 src tile
    for (int i = tid; i < TSZ * TSZ; i += 128) {
        int yy = i / TSZ, xx = i % TSZ;
        s_tile[i] = sbase[(size_t)(ty * TSZ + yy) * W + tx * TSZ + xx];
    }
    __syncthreads();

    // 121 candidate SSDs: one candidate per thread, fixed accumulation order
    // (duplicate candidates from border clamping stay bit-identical => same
    // tie-breaking as JAX first-occurrence argmin)
    if (tid < SSN * SSN) {
        int cy = tid / SSN, cx = tid % SSN;
        const float* wp = &s_win[cy * WINSZ + cx];
        float acc = 0.0f;
        for (int yy = 0; yy < TSZ; yy++) {
            #pragma unroll
            for (int xx = 0; xx < TSZ; xx++) {
                float d = wp[yy * WINSZ + xx] - s_tile[yy * TSZ + xx];
                acc = fmaf(d, d, acc);
            }
        }
        float ay = (float)(cy - (SRR + PD)) / (float)SSN;
        float ax = (float)(cx - (SRR + PD)) / (float)SSN;
        float sd = ay * ay + ax * ax;
        s_dist[tid] = acc * (1.0f / 256.0f) + 0.1f * sd;
    }
    __syncthreads();

    if (tid == 0) {
        // argmin over cropped 9x9, row-major, strict < (first occurrence)
        float best = 3.4e38f;
        int bk = 0;
        for (int k = 0; k < 81; k++) {
            float v = s_dist[(k / 9 + 1) * SSN + (k % 9 + 1)];
            if (v < best) { best = v; bk = k; }
        }
        int py = bk / 9, px = bk % 9;
        float offy = s_init[0] + (float)(py - SRR);
        float offx = s_init[1] + (float)(px - SRR);

        // subpixel refine on 3x3 neighborhood of dist_full (always in bounds)
        int fy = py + 1, fx = px + 1;
        float y00 = s_dist[(fy - 1) * SSN + fx - 1], y01 = s_dist[(fy - 1) * SSN + fx], y02 = s_dist[(fy - 1) * SSN + fx + 1];
        float y10 = s_dist[fy * SSN + fx - 1],       y11 = s_dist[fy * SSN + fx],       y12 = s_dist[fy * SSN + fx + 1];
        float y20 = s_dist[(fy + 1) * SSN + fx - 1], y21 = s_dist[(fy + 1) * SSN + fx], y22 = s_dist[(fy + 1) * SSN + fx + 1];

        float a11 = (y00 - 2.f * y01 + y02 + 2.f * y10 - 4.f * y11 + 2.f * y12 + y20 - 2.f * y21 + y22) * 0.25f;
        a11 = fmaxf(a11, 0.0f);
        float a22 = (y00 + 2.f * y01 + y02 - 2.f * y10 - 4.f * y11 - 2.f * y12 + y20 + 2.f * y21 + y22) * 0.25f;
        a22 = fmaxf(a22, 0.0f);
        float a12 = (y00 - y02 - y20 + y22) * 0.25f;
        float b1  = (-y00 + y02 - 2.f * y10 + 2.f * y12 - y20 + y22) * 0.125f;
        float b2  = (-y00 - 2.f * y01 - y02 + y20 + 2.f * y21 + y22) * 0.125f;

        float det = a11 * a22 - a12 * a12;
        float a12z = (det < 0.0f) ? 0.0f : a12;
        float mu_x = -(a22 * b1 - a12z * b2) / det;
        float mu_y = -(a11 * b2 - a12z * b1) / det;
        float mu_len = sqrtf(mu_y * mu_y + mu_x * mu_x);
        if (mu_len < 1.0f) { offx += mu_x; offy += mu_y; }  // false for NaN/inf, as in JAX

        if (outOff) {
            float* o = &outOff[(((size_t)n * nth + ty) * ntw + tx) * 2];
            o[0] = offy; o[1] = offx;
        }
        s_res[0] = offy; s_res[1] = offx; s_res[2] = best;
    }

    if (outPixOff) {
        __syncthreads();
        float offy = s_res[0], offx = s_res[1], mind = s_res[2];
        for (int i = tid; i < TSZ * TSZ; i += 128) {
            int yy = i / TSZ, xx = i % TSZ;
            size_t pidx = ((size_t)n * H + ty * TSZ + yy) * W + tx * TSZ + xx;
            outPixOff[pidx * 2 + 0] = offy;
            outPixOff[pidx * 2 + 1] = offx;
            outPixDist[pidx] = mind;
        }
    }
}

extern "C" void kernel_launch(void* const* d_in, const int* in_sizes, int n_in,
                              void* d_out, int out_size) {
    (void)in_sizes; (void)n_in; (void)out_size;
    const float* src = (const float*)d_in[0];
    const float* dst = (const float*)d_in[1];

    float *ps1, *ps2, *ps3, *pd1, *pd2, *pd3, *offA, *offB;
    cudaGetSymbolAddress((void**)&ps1, g_ps1);
    cudaGetSymbolAddress((void**)&ps2, g_ps2);
    cudaGetSymbolAddress((void**)&ps3, g_ps3);
    cudaGetSymbolAddress((void**)&pd1, g_pd1);
    cudaGetSymbolAddress((void**)&pd2, g_pd2);
    cudaGetSymbolAddress((void**)&pd3, g_pd3);
    cudaGetSymbolAddress((void**)&offA, g_offA);
    cudaGetSymbolAddress((void**)&offB, g_offB);

    float* outPixOff = (float*)d_out;                       // (4,512,512,2)
    float* outPixDist = (float*)d_out + (size_t)4 * 512 * 512 * 2;  // (4,512,512)

    dim3 b2(16, 16);
    blur_pool_kernel<<<dim3(16, 16, 8), b2>>>(src, dst, ps1, pd1, 512, 512);
    blur_pool_kernel<<<dim3(8, 8, 8), b2>>>(ps1, pd1, ps2, pd2, 256, 256);
    blur_pool_kernel<<<dim3(4, 4, 8), b2>>>(ps2, pd2, ps3, pd3, 128, 128);

    // coarse -> fine
    match_kernel<<<dim3(4, 4, 4), 128>>>(ps3, pd3, 64, 64, 4, 4, nullptr, offA, nullptr, nullptr);
    match_kernel<<<dim3(8, 8, 4), 128>>>(ps2, pd2, 128, 128, 8, 8, offA, offB, nullptr, nullptr);
    match_kernel<<<dim3(16, 16, 4), 128>>>(ps1, pd1, 256, 256, 16, 16, offB, offA, nullptr, nullptr);
    match_kernel<<<dim3(32, 32, 4), 128>>>(src, dst, 512, 512, 32, 32, offA, nullptr, outPixOff, outPixDist);
}

// round 3
// speedup vs baseline: 1.1263x; 1.1263x over previous
#include <cuda_runtime.h>

#define TSZ 16
#define SRR 4
#define PD 1
#define SSN 11          // 2*(SR+PADD)+1
#define WINSZ 26        // T + 2*(SR+PADD)
#define WINAREA (WINSZ*WINSZ)

// ---------------- scratch (no allocations allowed) ----------------
__device__ float g_ps1[4 * 256 * 256];
__device__ float g_pd1[4 * 256 * 256];
__device__ float g_ps2[4 * 128 * 128];
__device__ float g_pd2[4 * 128 * 128];
__device__ float g_ps3[4 * 64 * 64];
__device__ float g_pd3[4 * 64 * 64];
__device__ float g_off2[4 * 8 * 8 * 2];   // level-2 offsets (bridge between the two match kernels)

// ---------------- level0 -> level1: gaussian blur (5x5, zero-pad) + 2x2 avg pool ----------------
__global__ void blur_pool_kernel(const float* __restrict__ inS, const float* __restrict__ inD,
                                 float* __restrict__ outS, float* __restrict__ outD,
                                 int Hin, int Win2) {
    int Ho = Hin >> 1, Wo = Win2 >> 1;
    int ox = blockIdx.x * blockDim.x + threadIdx.x;
    int oy = blockIdx.y * blockDim.y + threadIdx.y;
    if (ox >= Wo || oy >= Ho) return;
    int z = blockIdx.z;  // 0..3 src, 4..7 dst
    const float* in = (z < 4 ? inS : inD) + (size_t)(z & 3) * Hin * Win2;
    float* out = (z < 4 ? outS : outD) + (size_t)(z & 3) * Ho * Wo;

    const float w0 = 0.13533528323661270f;  // exp(-2)
    const float w1 = 0.60653065971263342f;  // exp(-0.5)
    const float wv[5] = {w0, w1, 1.0f, w1, w0};
    const float ksum = 1.0f + 2.0f * w1 + 2.0f * w0;
    const float norm = 1.0f / (ksum * ksum);

    float acc = 0.0f;
    #pragma unroll
    for (int py = 0; py < 2; py++) {
        #pragma unroll
        for (int px = 0; px < 2; px++) {
            int cy = 2 * oy + py, cx = 2 * ox + px;
            float s = 0.0f;
            #pragma unroll
            for (int a = 0; a < 5; a++) {
                int yy = cy + a - 2;
                if (yy < 0 || yy >= Hin) continue;
                #pragma unroll
                for (int b = 0; b < 5; b++) {
                    int xx = cx + b - 2;
                    if (xx < 0 || xx >= Win2) continue;
                    s += (wv[a] * wv[b] * norm) * in[(size_t)yy * Win2 + xx];
                }
            }
            acc += s;
        }
    }
    out[(size_t)oy * Wo + ox] = acc * 0.25f;
}

// ---------------- level1 -> level2 + level3 fused ----------------
// One CTA per 8x8 level-3 tile: loads a 44x44 level-1 halo, computes a 20x20
// level-2 patch (writes the central 16x16), then the 8x8 level-3 tile.
__global__ void __launch_bounds__(256) blur23_kernel(
    const float* __restrict__ inS, const float* __restrict__ inD,
    float* __restrict__ o2S, float* __restrict__ o2D,
    float* __restrict__ o3S, float* __restrict__ o3D)
{
    __shared__ float l1[44 * 44];
    __shared__ float l2[20 * 20];
    int bx = blockIdx.x, by = blockIdx.y, z = blockIdx.z;
    int tid = threadIdx.x;
    const float* in = (z < 4 ? inS : inD) + (size_t)(z & 3) * 256 * 256;
    float* o2 = (z < 4 ? o2S : o2D) + (size_t)(z & 3) * 128 * 128;
    float* o3 = (z < 4 ? o3S : o3D) + (size_t)(z & 3) * 64 * 64;

    const float w0 = 0.13533528323661270f;
    const float w1 = 0.60653065971263342f;
    const float wv[5] = {w0, w1, 1.0f, w1, w0};
    const float ksum = 1.0f + 2.0f * w1 + 2.0f * w0;
    const float norm = 1.0f / (ksum * ksum);

    int R0 = 32 * by - 6, C0 = 32 * bx - 6;
    for (int i = tid; i < 44 * 44; i += 256) {
        int r = i / 44, c = i - r * 44;
        int gy = R0 + r, gx = C0 + c;
        l1[i] = (gy >= 0 && gy < 256 && gx >= 0 && gx < 256) ? in[(size_t)gy * 256 + gx] : 0.0f;
    }
    __syncthreads();

    // level2 local 20x20 (global rows 16*by-2 .. 16*by+17)
    for (int i = tid; i < 400; i += 256) {
        int r = i / 20, c = i - r * 20;
        int g2y = 16 * by - 2 + r, g2x = 16 * bx - 2 + c;
        float acc = 0.0f;
        if (g2y >= 0 && g2y < 128 && g2x >= 0 && g2x < 128) {
            #pragma unroll
            for (int py = 0; py < 2; py++) {
                #pragma unroll
                for (int px = 0; px < 2; px++) {
                    float s = 0.0f;
                    #pragma unroll
                    for (int a = 0; a < 5; a++)
                        #pragma unroll
                        for (int b = 0; b < 5; b++)
                            s += (wv[a] * wv[b] * norm) * l1[(2 * r + py + a) * 44 + (2 * c + px + b)];
                    acc += s;
                }
            }
            acc *= 0.25f;
        }
        l2[i] = acc;
        if (r >= 2 && r < 18 && c >= 2 && c < 18)
            o2[(size_t)(16 * by + r - 2) * 128 + (16 * bx + c - 2)] = acc;
    }
    __syncthreads();

    // level3 8x8
    if (tid < 64) {
        int t = tid >> 3, u = tid & 7;
        float acc = 0.0f;
        #pragma unroll
        for (int py = 0; py < 2; py++) {
            #pragma unroll
            for (int px = 0; px < 2; px++) {
                float s = 0.0f;
                #pragma unroll
                for (int a = 0; a < 5; a++)
                    #pragma unroll
                    for (int b = 0; b < 5; b++)
                        s += (wv[a] * wv[b] * norm) * l2[(2 * t + py + a) * 20 + (2 * u + px + b)];
                acc += s;
            }
        }
        o3[(size_t)(8 * by + t) * 64 + (8 * bx + u)] = acc * 0.25f;
    }
}

// ---------------- block matching ----------------
__device__ __forceinline__ void bar_sync_128(int id) {
    asm volatile("bar.sync %0, %1;" :: "r"(id), "r"(128) : "memory");
}

// One tile match executed by a 128-thread group (gl = 0..127, barId unique per group).
// Result (offy, offx, min_dist) published to sres[0..2], visible to the whole group on return.
__device__ __forceinline__ void tile_match(
    int ty, int tx, float inity, float initx,
    const float* __restrict__ sbase, const float* __restrict__ dbase,
    int H, int W, int gl, int barId,
    float* swin, float* stile, float* sdist,
    unsigned long long* skey, float* sres, bool loadTile)
{
    int oy = (int)inity, ox = (int)initx;  // init offsets are integral
    int y0 = ty * TSZ + oy - (SRR + PD);
    int x0 = tx * TSZ + ox - (SRR + PD);

    // gather 26x26 dst window with clamped indices
    for (int i = gl; i < WINAREA; i += 128) {
        int wy = i / WINSZ, wx = i - wy * WINSZ;
        int gy = min(max(y0 + wy, 0), H - 1);
        int gx = min(max(x0 + wx, 0), W - 1);
        swin[i] = dbase[(size_t)gy * W + gx];
    }
    if (loadTile) {
        for (int i = gl; i < TSZ * TSZ; i += 128) {
            int yy = i >> 4, xx = i & 15;
            stile[i] = sbase[(size_t)(ty * TSZ + yy) * W + tx * TSZ + xx];
        }
    }
    if (gl == 0) *skey = 0xFFFFFFFFFFFFFFFFULL;
    bar_sync_128(barId);

    // 121 candidate SSDs, one per thread. 4 accumulators (uniform order across
    // candidates => duplicate clamped candidates stay bit-identical => JAX tie
    // semantics preserved). Tile read via float4 (aligned), window scalar.
    if (gl < SSN * SSN) {
        int cy = gl / SSN, cx = gl - cy * SSN;
        const float* wp = &swin[cy * WINSZ + cx];
        float a0 = 0.f, a1 = 0.f, a2 = 0.f, a3 = 0.f;
        #pragma unroll
        for (int yy = 0; yy < TSZ; yy++) {
            const float* w = wp + yy * WINSZ;
            const float4* t = (const float4*)(stile + yy * TSZ);
            #pragma unroll
            for (int q = 0; q < 4; q++) {
                float4 tv = t[q];
                float d0 = w[4 * q + 0] - tv.x; a0 = fmaf(d0, d0, a0);
                float d1 = w[4 * q + 1] - tv.y; a1 = fmaf(d1, d1, a1);
                float d2 = w[4 * q + 2] - tv.z; a2 = fmaf(d2, d2, a2);
                float d3 = w[4 * q + 3] - tv.w; a3 = fmaf(d3, d3, a3);
            }
        }
        float acc = (a0 + a1) + (a2 + a3);
        float ay = (float)(cy - (SRR + PD)) / (float)SSN;
        float ax = (float)(cx - (SRR + PD)) / (float)SSN;
        sdist[gl] = acc * (1.0f / 256.0f) + 0.1f * (ay * ay + ax * ax);
    }
    bar_sync_128(barId);

    // parallel argmin over the cropped 9x9 (first occurrence == smallest index on tie)
    if (gl < 81) {
        int py = gl / 9, px = gl - py * 9;
        float v = sdist[(py + 1) * SSN + (px + 1)];
        unsigned long long key = ((unsigned long long)__float_as_uint(v) << 32) | (unsigned)gl;
        atomicMin(skey, key);
    }
    bar_sync_128(barId);

    if (gl == 0) {
        unsigned long long key = *skey;
        int bk = (int)(key & 0xFFFFFFFFu);
        float best = __uint_as_float((unsigned)(key >> 32));
        int py = bk / 9, px = bk - py * 9;
        float offy = inity + (float)(py - SRR);
        float offx = initx + (float)(px - SRR);

        int fy = py + 1, fx = px + 1;
        float y00 = sdist[(fy - 1) * SSN + fx - 1], y01 = sdist[(fy - 1) * SSN + fx], y02 = sdist[(fy - 1) * SSN + fx + 1];
        float y10 = sdist[fy * SSN + fx - 1],       y11 = sdist[fy * SSN + fx],       y12 = sdist[fy * SSN + fx + 1];
        float y20 = sdist[(fy + 1) * SSN + fx - 1], y21 = sdist[(fy + 1) * SSN + fx], y22 = sdist[(fy + 1) * SSN + fx + 1];

        float a11 = (y00 - 2.f * y01 + y02 + 2.f * y10 - 4.f * y11 + 2.f * y12 + y20 - 2.f * y21 + y22) * 0.25f;
        a11 = fmaxf(a11, 0.0f);
        float a22 = (y00 + 2.f * y01 + y02 - 2.f * y10 - 4.f * y11 - 2.f * y12 + y20 + 2.f * y21 + y22) * 0.25f;
        a22 = fmaxf(a22, 0.0f);
        float a12 = (y00 - y02 - y20 + y22) * 0.25f;
        float b1  = (-y00 + y02 - 2.f * y10 + 2.f * y12 - y20 + y22) * 0.125f;
        float b2  = (-y00 - 2.f * y01 - y02 + y20 + 2.f * y21 + y22) * 0.125f;

        float det = a11 * a22 - a12 * a12;
        float a12z = (det < 0.0f) ? 0.0f : a12;
        float mu_x = -(a22 * b1 - a12z * b2) / det;
        float mu_y = -(a11 * b2 - a12z * b1) / det;
        float mu_len = sqrtf(mu_y * mu_y + mu_x * mu_x);
        if (mu_len < 1.0f) { offx += mu_x; offy += mu_y; }  // false for NaN/inf, as in JAX

        sres[0] = offy; sres[1] = offx; sres[2] = best;
    }
    bar_sync_128(barId);
}

// Fused two-level match: one CTA = one parent tile + its 4 child tiles.
// Threads 0..127 match the parent while threads 128..511 preload the 4 child src
// tiles; then 4 independent 128-thread groups match the children in parallel.
__global__ void __launch_bounds__(512) match2_kernel(
    const float* __restrict__ srcP, const float* __restrict__ dstP, int Hp, int Wp,
    const float* __restrict__ srcC, const float* __restrict__ dstC, int Hc, int Wc,
    const float* __restrict__ grandOff, int ntwg,
    float* __restrict__ outChildOff, int ntwc,
    float* __restrict__ outPixOff, float* __restrict__ outPixDist)
{
    __shared__ float s_win[4][WINAREA];
    __shared__ float s_tile[4][TSZ * TSZ];
    __shared__ float s_dist[4][SSN * SSN];
    __shared__ unsigned long long s_key[4];
    __shared__ float s_res[4][3];
    __shared__ float s_ptile[TSZ * TSZ];
    __shared__ float s_pres[3];
    __shared__ unsigned long long s_pkey;

    int tx = blockIdx.x, ty = blockIdx.y, n = blockIdx.z;
    int tid = threadIdx.x;
    const float* sPb = srcP + (size_t)n * Hp * Wp;
    const float* dPb = dstP + (size_t)n * Hp * Wp;
    const float* sCb = srcC + (size_t)n * Hc * Wc;
    const float* dCb = dstC + (size_t)n * Hc * Wc;

    // ---- stage 1: parent tile (group 0) + child tile preload (threads >=128) ----
    if (tid < 128) {
        float inity = 0.0f, initx = 0.0f;
        if (grandOff) {
            const float* p = &grandOff[(((size_t)n * ntwg + (ty >> 1)) * ntwg + (tx >> 1)) * 2];
            float o0 = 2.0f * p[0], o1 = 2.0f * p[1];
            float fy = (float)(ty * TSZ), fx = (float)(tx * TSZ);
            inity = rintf(fminf(fmaxf(o0 + fy, 0.0f), (float)(Hp - TSZ)) - fy);
            initx = rintf(fminf(fmaxf(o1 + fx, 0.0f), (float)(Wp - TSZ)) - fx);
        }
        tile_match(ty, tx, inity, initx, sPb, dPb, Hp, Wp,
                   tid, /*barId=*/1, s_win[0], s_ptile, s_dist[0], &s_pkey, s_pres, true);
    } else {
        // preload all 4 child src tiles
        for (int i = tid - 128; i < 4 * TSZ * TSZ; i += 384) {
            int child = i >> 8;
            int j = i & 255;
            int yy = j >> 4, xx = j & 15;
            int cty = 2 * ty + (child >> 1), ctx = 2 * tx + (child & 1);
            s_tile[child][j] = sCb[(size_t)(cty * TSZ + yy) * Wc + ctx * TSZ + xx];
        }
    }
    __syncthreads();

    // ---- stage 2: 4 children in parallel ----
    int group = tid >> 7, gl = tid & 127;
    int cty = 2 * ty + (group >> 1), ctx = 2 * tx + (group & 1);
    float o0 = 2.0f * s_pres[0], o1 = 2.0f * s_pres[1];
    float fy = (float)(cty * TSZ), fx = (float)(ctx * TSZ);
    float ciy = rintf(fminf(fmaxf(o0 + fy, 0.0f), (float)(Hc - TSZ)) - fy);
    float cix = rintf(fminf(fmaxf(o1 + fx, 0.0f), (float)(Wc - TSZ)) - fx);

    tile_match(cty, ctx, ciy, cix, sCb, dCb, Hc, Wc,
               gl, /*barId=*/1 + group, s_win[group], s_tile[group], s_dist[group],
               &s_key[group], s_res[group], false);

    if (outChildOff) {
        if (gl == 0) {
            float* o = &outChildOff[(((size_t)n * ntwc + cty) * ntwc + ctx) * 2];
            o[0] = s_res[group][0];
            o[1] = s_res[group][1];
        }
    }
    if (outPixOff) {
        float offy = s_res[group][0], offx = s_res[group][1], mind = s_res[group][2];
        for (int i = gl; i < TSZ * TSZ; i += 128) {
            int yy = i >> 4, xx = i & 15;
            size_t pidx = ((size_t)n * Hc + cty * TSZ + yy) * Wc + ctx * TSZ + xx;
            outPixOff[pidx * 2 + 0] = offy;
            outPixOff[pidx * 2 + 1] = offx;
            outPixDist[pidx] = mind;
        }
    }
}

extern "C" void kernel_launch(void* const* d_in, const int* in_sizes, int n_in,
                              void* d_out, int out_size) {
    (void)in_sizes; (void)n_in; (void)out_size;
    const float* src = (const float*)d_in[0];
    const float* dst = (const float*)d_in[1];

    float *ps1, *ps2, *ps3, *pd1, *pd2, *pd3, *off2;
    cudaGetSymbolAddress((void**)&ps1, g_ps1);
    cudaGetSymbolAddress((void**)&ps2, g_ps2);
    cudaGetSymbolAddress((void**)&ps3, g_ps3);
    cudaGetSymbolAddress((void**)&pd1, g_pd1);
    cudaGetSymbolAddress((void**)&pd2, g_pd2);
    cudaGetSymbolAddress((void**)&pd3, g_pd3);
    cudaGetSymbolAddress((void**)&off2, g_off2);

    float* outPixOff = (float*)d_out;                              // (4,512,512,2)
    float* outPixDist = (float*)d_out + (size_t)4 * 512 * 512 * 2; // (4,512,512)

    // level0 -> level1
    blur_pool_kernel<<<dim3(16, 16, 8), dim3(16, 16)>>>(src, dst, ps1, pd1, 512, 512);
    // level1 -> level2 + level3 (fused)
    blur23_kernel<<<dim3(8, 8, 8), 256>>>(ps1, pd1, ps2, pd2, ps3, pd3);

    // match: levels 3+2 fused, then levels 1+0 fused
    match2_kernel<<<dim3(4, 4, 4), 512>>>(ps3, pd3, 64, 64, ps2, pd2, 128, 128,
                                          nullptr, 0, off2, 8, nullptr, nullptr);
    match2_kernel<<<dim3(16, 16, 4), 512>>>(ps1, pd1, 256, 256, src, dst, 512, 512,
                                            off2, 8, nullptr, 0, outPixOff, outPixDist);
}

// round 5
// speedup vs baseline: 1.3100x; 1.1631x over previous
#include <cuda_runtime.h>

#define TSZ 16
#define SRR 4
#define PD 1
#define SSN 11          // 2*(SR+PADD)+1
#define WINSZ 26        // T + 2*(SR+PADD)
#define WINAREA (WINSZ*WINSZ)

// ---------------- scratch (no allocations allowed) ----------------
__device__ float g_ps1[4 * 256 * 256];
__device__ float g_pd1[4 * 256 * 256];
__device__ float g_ps2[4 * 128 * 128];
__device__ float g_pd2[4 * 128 * 128];
__device__ float g_ps3[4 * 64 * 64];
__device__ float g_pd3[4 * 64 * 64];
__device__ float g_off2[4 * 8 * 8 * 2];

// ---------------- level0 -> level1: gaussian blur (5x5, zero-pad) + 2x2 avg pool ----------------
__global__ void blur_pool_kernel(const float* __restrict__ inS, const float* __restrict__ inD,
                                 float* __restrict__ outS, float* __restrict__ outD,
                                 int Hin, int Win2) {
    int Ho = Hin >> 1, Wo = Win2 >> 1;
    int ox = blockIdx.x * blockDim.x + threadIdx.x;
    int oy = blockIdx.y * blockDim.y + threadIdx.y;
    if (ox >= Wo || oy >= Ho) return;
    int z = blockIdx.z;  // 0..3 src, 4..7 dst
    const float* in = (z < 4 ? inS : inD) + (size_t)(z & 3) * Hin * Win2;
    float* out = (z < 4 ? outS : outD) + (size_t)(z & 3) * Ho * Wo;

    const float w0 = 0.13533528323661270f;  // exp(-2)
    const float w1 = 0.60653065971263342f;  // exp(-0.5)
    const float wv[5] = {w0, w1, 1.0f, w1, w0};
    const float ksum = 1.0f + 2.0f * w1 + 2.0f * w0;
    const float norm = 1.0f / (ksum * ksum);

    float acc = 0.0f;
    #pragma unroll
    for (int py = 0; py < 2; py++) {
        #pragma unroll
        for (int px = 0; px < 2; px++) {
            int cy = 2 * oy + py, cx = 2 * ox + px;
            float s = 0.0f;
            #pragma unroll
            for (int a = 0; a < 5; a++) {
                int yy = cy + a - 2;
                if (yy < 0 || yy >= Hin) continue;
                #pragma unroll
                for (int b = 0; b < 5; b++) {
                    int xx = cx + b - 2;
                    if (xx < 0 || xx >= Win2) continue;
                    s += (wv[a] * wv[b] * norm) * in[(size_t)yy * Win2 + xx];
                }
            }
            acc += s;
        }
    }
    out[(size_t)oy * Wo + ox] = acc * 0.25f;
}

// ---------------- level1 -> level2 + level3 fused ----------------
__global__ void __launch_bounds__(256) blur23_kernel(
    const float* __restrict__ inS, const float* __restrict__ inD,
    float* __restrict__ o2S, float* __restrict__ o2D,
    float* __restrict__ o3S, float* __restrict__ o3D)
{
    __shared__ float l1[44 * 44];
    __shared__ float l2[20 * 20];
    int bx = blockIdx.x, by = blockIdx.y, z = blockIdx.z;
    int tid = threadIdx.x;
    const float* in = (z < 4 ? inS : inD) + (size_t)(z & 3) * 256 * 256;
    float* o2 = (z < 4 ? o2S : o2D) + (size_t)(z & 3) * 128 * 128;
    float* o3 = (z < 4 ? o3S : o3D) + (size_t)(z & 3) * 64 * 64;

    const float w0 = 0.13533528323661270f;
    const float w1 = 0.60653065971263342f;
    const float wv[5] = {w0, w1, 1.0f, w1, w0};
    const float ksum = 1.0f + 2.0f * w1 + 2.0f * w0;
    const float norm = 1.0f / (ksum * ksum);

    int R0 = 32 * by - 6, C0 = 32 * bx - 6;
    for (int i = tid; i < 44 * 44; i += 256) {
        int r = i / 44, c = i - r * 44;
        int gy = R0 + r, gx = C0 + c;
        l1[i] = (gy >= 0 && gy < 256 && gx >= 0 && gx < 256) ? in[(size_t)gy * 256 + gx] : 0.0f;
    }
    __syncthreads();

    for (int i = tid; i < 400; i += 256) {
        int r = i / 20, c = i - r * 20;
        int g2y = 16 * by - 2 + r, g2x = 16 * bx - 2 + c;
        float acc = 0.0f;
        if (g2y >= 0 && g2y < 128 && g2x >= 0 && g2x < 128) {
            #pragma unroll
            for (int py = 0; py < 2; py++) {
                #pragma unroll
                for (int px = 0; px < 2; px++) {
                    float s = 0.0f;
                    #pragma unroll
                    for (int a = 0; a < 5; a++)
                        #pragma unroll
                        for (int b = 0; b < 5; b++)
                            s += (wv[a] * wv[b] * norm) * l1[(2 * r + py + a) * 44 + (2 * c + px + b)];
                    acc += s;
                }
            }
            acc *= 0.25f;
        }
        l2[i] = acc;
        if (r >= 2 && r < 18 && c >= 2 && c < 18)
            o2[(size_t)(16 * by + r - 2) * 128 + (16 * bx + c - 2)] = acc;
    }
    __syncthreads();

    if (tid < 64) {
        int t = tid >> 3, u = tid & 7;
        float acc = 0.0f;
        #pragma unroll
        for (int py = 0; py < 2; py++) {
            #pragma unroll
            for (int px = 0; px < 2; px++) {
                float s = 0.0f;
                #pragma unroll
                for (int a = 0; a < 5; a++)
                    #pragma unroll
                    for (int b = 0; b < 5; b++)
                        s += (wv[a] * wv[b] * norm) * l2[(2 * t + py + a) * 20 + (2 * u + px + b)];
                acc += s;
            }
        }
        o3[(size_t)(8 * by + t) * 64 + (8 * bx + u)] = acc * 0.25f;
    }
}

// ---------------- block matching ----------------
__device__ __forceinline__ void bar_sync_128(int id) {
    asm volatile("bar.sync %0, %1;" :: "r"(id), "r"(128) : "memory");
}

// One tile match executed by a 128-thread group (gl = 0..127, barId unique per group).
// SSD phase: thread (cy, h) computes all 11 cx-candidates over 2 tile rows from
// registers; 30 LDS amortized over 176 FMAs per row. h-partials reduced via shfl.
__device__ __forceinline__ void tile_match(
    int ty, int tx, float inity, float initx,
    const float* __restrict__ sbase, const float* __restrict__ dbase,
    int H, int W, int gl, int barId,
    float* swin, float* stile, float* sdist,
    unsigned long long* skey, float* sres, bool loadTile)
{
    int oy = (int)inity, ox = (int)initx;  // init offsets are integral
    int y0 = ty * TSZ + oy - (SRR + PD);
    int x0 = tx * TSZ + ox - (SRR + PD);

    // gather 26x26 dst window with clamped indices
    for (int i = gl; i < WINAREA; i += 128) {
        int wy = i / WINSZ, wx = i - wy * WINSZ;
        int gy = min(max(y0 + wy, 0), H - 1);
        int gx = min(max(x0 + wx, 0), W - 1);
        swin[i] = dbase[(size_t)gy * W + gx];
    }
    if (loadTile) {
        for (int i = gl; i < TSZ * TSZ; i += 128) {
            int yy = i >> 4, xx = i & 15;
            stile[i] = sbase[(size_t)(ty * TSZ + yy) * W + tx * TSZ + xx];
        }
    }
    if (gl == 0) *skey = 0xFFFFFFFFFFFFFFFFULL;
    bar_sync_128(barId);

    // ---- SSD: lanes 0..95 (warps 0..2 of the group, full warps for shfl) ----
    if (gl < 96) {
        int cy = gl >> 3;           // 0..11 (11 = padding lanes, clamped)
        int h = gl & 7;             // 0..7 -> rows 2h, 2h+1
        int cyc = (cy < SSN) ? cy : 0;

        float acc[SSN];
        #pragma unroll
        for (int c = 0; c < SSN; c++) acc[c] = 0.0f;

        #pragma unroll 1
        for (int rr = 0; rr < 2; rr++) {
            int yy = 2 * h + rr;
            const float* wr = swin + (cyc + yy) * WINSZ;
            float wreg[WINSZ];
            #pragma unroll
            for (int k = 0; k < WINSZ; k++) wreg[k] = wr[k];
            float treg[TSZ];
            const float4* t4 = (const float4*)(stile + yy * TSZ);
            #pragma unroll
            for (int q = 0; q < 4; q++) {
                float4 v = t4[q];
                treg[4 * q + 0] = v.x; treg[4 * q + 1] = v.y;
                treg[4 * q + 2] = v.z; treg[4 * q + 3] = v.w;
            }
            #pragma unroll
            for (int cx = 0; cx < SSN; cx++) {
                #pragma unroll
                for (int xx = 0; xx < TSZ; xx++) {
                    float d = wreg[cx + xx] - treg[xx];
                    acc[cx] = fmaf(d, d, acc[cx]);
                }
            }
        }
        // reduce over the 8 h-lanes (contiguous groups of 8 within a warp)
        #pragma unroll
        for (int c = 0; c < SSN; c++) {
            acc[c] += __shfl_down_sync(0xFFFFFFFFu, acc[c], 4);
            acc[c] += __shfl_down_sync(0xFFFFFFFFu, acc[c], 2);
            acc[c] += __shfl_down_sync(0xFFFFFFFFu, acc[c], 1);
        }
        if (h == 0 && cy < SSN) {
            float ay = (float)(cy - (SRR + PD)) / (float)SSN;
            #pragma unroll
            for (int cx = 0; cx < SSN; cx++) {
                float ax = (float)(cx - (SRR + PD)) / (float)SSN;
                sdist[cy * SSN + cx] = acc[cx] * (1.0f / 256.0f) + 0.1f * (ay * ay + ax * ax);
            }
        }
    }
    bar_sync_128(barId);

    // parallel argmin over the cropped 9x9 (first occurrence == smallest index on tie)
    if (gl < 81) {
        int py = gl / 9, px = gl - py * 9;
        float v = sdist[(py + 1) * SSN + (px + 1)];
        unsigned long long key = ((unsigned long long)__float_as_uint(v) << 32) | (unsigned)gl;
        atomicMin(skey, key);
    }
    bar_sync_128(barId);

    if (gl == 0) {
        unsigned long long key = *skey;
        int bk = (int)(key & 0xFFFFFFFFu);
        float best = __uint_as_float((unsigned)(key >> 32));
        int py = bk / 9, px = bk - py * 9;
        float offy = inity + (float)(py - SRR);
        float offx = initx + (float)(px - SRR);

        int fy = py + 1, fx = px + 1;
        float y00 = sdist[(fy - 1) * SSN + fx - 1], y01 = sdist[(fy - 1) * SSN + fx], y02 = sdist[(fy - 1) * SSN + fx + 1];
        float y10 = sdist[fy * SSN + fx - 1],       y11 = sdist[fy * SSN + fx],       y12 = sdist[fy * SSN + fx + 1];
        float y20 = sdist[(fy + 1) * SSN + fx - 1], y21 = sdist[(fy + 1) * SSN + fx], y22 = sdist[(fy + 1) * SSN + fx + 1];

        float a11 = (y00 - 2.f * y01 + y02 + 2.f * y10 - 4.f * y11 + 2.f * y12 + y20 - 2.f * y21 + y22) * 0.25f;
        a11 = fmaxf(a11, 0.0f);
        float a22 = (y00 + 2.f * y01 + y02 - 2.f * y10 - 4.f * y11 - 2.f * y12 + y20 + 2.f * y21 + y22) * 0.25f;
        a22 = fmaxf(a22, 0.0f);
        float a12 = (y00 - y02 - y20 + y22) * 0.25f;
        float b1  = (-y00 + y02 - 2.f * y10 + 2.f * y12 - y20 + y22) * 0.125f;
        float b2  = (-y00 - 2.f * y01 - y02 + y20 + 2.f * y21 + y22) * 0.125f;

        float det = a11 * a22 - a12 * a12;
        float a12z = (det < 0.0f) ? 0.0f : a12;
        float mu_x = -(a22 * b1 - a12z * b2) / det;
        float mu_y = -(a11 * b2 - a12z * b1) / det;
        float mu_len = sqrtf(mu_y * mu_y + mu_x * mu_x);
        if (mu_len < 1.0f) { offx += mu_x; offy += mu_y; }  // false for NaN/inf, as in JAX

        sres[0] = offy; sres[1] = offx; sres[2] = best;
    }
    bar_sync_128(barId);
}

// Fused two-level match: one CTA = one parent tile + its 4 child tiles.
__global__ void __launch_bounds__(512) match2_kernel(
    const float* __restrict__ srcP, const float* __restrict__ dstP, int Hp, int Wp,
    const float* __restrict__ srcC, const float* __restrict__ dstC, int Hc, int Wc,
    const float* __restrict__ grandOff, int ntwg,
    float* __restrict__ outChildOff, int ntwc,
    float* __restrict__ outPixOff, float* __restrict__ outPixDist)
{
    __shared__ float s_win[4][WINAREA];
    __shared__ float s_tile[4][TSZ * TSZ];
    __shared__ float s_dist[4][SSN * SSN];
    __shared__ unsigned long long s_key[4];
    __shared__ float s_res[4][3];
    __shared__ float s_ptile[TSZ * TSZ];
    __shared__ float s_pres[3];
    __shared__ unsigned long long s_pkey;

    int tx = blockIdx.x, ty = blockIdx.y, n = blockIdx.z;
    int tid = threadIdx.x;
    const float* sPb = srcP + (size_t)n * Hp * Wp;
    const float* dPb = dstP + (size_t)n * Hp * Wp;
    const float* sCb = srcC + (size_t)n * Hc * Wc;
    const float* dCb = dstC + (size_t)n * Hc * Wc;

    // ---- stage 1: parent tile (group 0) + child tile preload (threads >=128) ----
    if (tid < 128) {
        float inity = 0.0f, initx = 0.0f;
        if (grandOff) {
            const float* p = &grandOff[(((size_t)n * ntwg + (ty >> 1)) * ntwg + (tx >> 1)) * 2];
            float o0 = 2.0f * p[0], o1 = 2.0f * p[1];
            float fy = (float)(ty * TSZ), fx = (float)(tx * TSZ);
            inity = rintf(fminf(fmaxf(o0 + fy, 0.0f), (float)(Hp - TSZ)) - fy);
            initx = rintf(fminf(fmaxf(o1 + fx, 0.0f), (float)(Wp - TSZ)) - fx);
        }
        tile_match(ty, tx, inity, initx, sPb, dPb, Hp, Wp,
                   tid, /*barId=*/1, s_win[0], s_ptile, s_dist[0], &s_pkey, s_pres, true);
    } else {
        for (int i = tid - 128; i < 4 * TSZ * TSZ; i += 384) {
            int child = i >> 8;
            int j = i & 255;
            int yy = j >> 4, xx = j & 15;
            int cty = 2 * ty + (child >> 1), ctx = 2 * tx + (child & 1);
            s_tile[child][j] = sCb[(size_t)(cty * TSZ + yy) * Wc + ctx * TSZ + xx];
        }
    }
    __syncthreads();

    // ---- stage 2: 4 children in parallel ----
    int group = tid >> 7, gl = tid & 127;
    int cty = 2 * ty + (group >> 1), ctx = 2 * tx + (group & 1);
    float o0 = 2.0f * s_pres[0], o1 = 2.0f * s_pres[1];
    float fy = (float)(cty * TSZ), fx = (float)(ctx * TSZ);
    float ciy = rintf(fminf(fmaxf(o0 + fy, 0.0f), (float)(Hc - TSZ)) - fy);
    float cix = rintf(fminf(fmaxf(o1 + fx, 0.0f), (float)(Wc - TSZ)) - fx);

    tile_match(cty, ctx, ciy, cix, sCb, dCb, Hc, Wc,
               gl, /*barId=*/1 + group, s_win[group], s_tile[group], s_dist[group],
               &s_key[group], s_res[group], false);

    if (outChildOff) {
        if (gl == 0) {
            float* o = &outChildOff[(((size_t)n * ntwc + cty) * ntwc + ctx) * 2];
            o[0] = s_res[group][0];
            o[1] = s_res[group][1];
        }
    }
    if (outPixOff) {
        float offy = s_res[group][0], offx = s_res[group][1], mind = s_res[group][2];
        float2* po = (float2*)outPixOff;
        float2 ov = make_float2(offy, offx);
        for (int i = gl; i < TSZ * TSZ; i += 128) {
            int yy = i >> 4, xx = i & 15;
            size_t pidx = ((size_t)n * Hc + cty * TSZ + yy) * Wc + ctx * TSZ + xx;
            po[pidx] = ov;
            outPixDist[pidx] = mind;
        }
    }
}

extern "C" void kernel_launch(void* const* d_in, const int* in_sizes, int n_in,
                              void* d_out, int out_size) {
    (void)in_sizes; (void)n_in; (void)out_size;
    const float* src = (const float*)d_in[0];
    const float* dst = (const float*)d_in[1];

    float *ps1, *ps2, *ps3, *pd1, *pd2, *pd3, *off2;
    cudaGetSymbolAddress((void**)&ps1, g_ps1);
    cudaGetSymbolAddress((void**)&ps2, g_ps2);
    cudaGetSymbolAddress((void**)&ps3, g_ps3);
    cudaGetSymbolAddress((void**)&pd1, g_pd1);
    cudaGetSymbolAddress((void**)&pd2, g_pd2);
    cudaGetSymbolAddress((void**)&pd3, g_pd3);
    cudaGetSymbolAddress((void**)&off2, g_off2);

    float* outPixOff = (float*)d_out;                              // (4,512,512,2)
    float* outPixDist = (float*)d_out + (size_t)4 * 512 * 512 * 2; // (4,512,512)

    blur_pool_kernel<<<dim3(16, 16, 8), dim3(16, 16)>>>(src, dst, ps1, pd1, 512, 512);
    blur23_kernel<<<dim3(8, 8, 8), 256>>>(ps1, pd1, ps2, pd2, ps3, pd3);

    match2_kernel<<<dim3(4, 4, 4), 512>>>(ps3, pd3, 64, 64, ps2, pd2, 128, 128,
                                          nullptr, 0, off2, 8, nullptr, nullptr);
    match2_kernel<<<dim3(16, 16, 4), 512>>>(ps1, pd1, 256, 256, src, dst, 512, 512,
                                            off2, 8, nullptr, 0, outPixOff, outPixDist);
}

// round 7
// speedup vs baseline: 1.5953x; 1.2178x over previous
#include <cuda_runtime.h>

#define TSZ 16
#define SRR 4
#define PD 1
#define SSN 11          // 2*(SR+PADD)+1
#define WINSZ 26        // T + 2*(SR+PADD)
#define WINAREA (WINSZ*WINSZ)

// ---------------- scratch (no allocations allowed) ----------------
__device__ float g_ps1[4 * 256 * 256];
__device__ float g_pd1[4 * 256 * 256];
__device__ float g_ps2[4 * 128 * 128];
__device__ float g_pd2[4 * 128 * 128];
__device__ float g_ps3[4 * 64 * 64];
__device__ float g_pd3[4 * 64 * 64];
__device__ float g_off2[4 * 8 * 8 * 2];

// ---------------- fully fused pyramid: L0 -> L1 -> L2 -> L3 in one kernel ----------------
// CTA per 8x8 L3 tile (grid 8x8x8). Computes a 44x44 L1 patch from a 92x92 L0 halo
// (1.9x redundant vs separate kernels -- compute is free here), then L2, then L3.
// Tap order is IDENTICAL to the previous separate blur kernels; out-of-image taps
// read smem zeros (x + 0.0f is exact for the non-negative values here), so all
// pyramid values are bit-identical to the previously passing version.
__global__ void __launch_bounds__(256) blur_all_kernel(
    const float* __restrict__ inS, const float* __restrict__ inD,
    float* __restrict__ o1S, float* __restrict__ o1D,
    float* __restrict__ o2S, float* __restrict__ o2D,
    float* __restrict__ o3S, float* __restrict__ o3D)
{
    __shared__ float l0[92 * 92];
    __shared__ float l1[44 * 44];
    __shared__ float l2[20 * 20];

    int bx = blockIdx.x, by = blockIdx.y, z = blockIdx.z;
    int tid = threadIdx.x;
    const float* in = (z < 4 ? inS : inD) + (size_t)(z & 3) * 512 * 512;
    float* o1 = (z < 4 ? o1S : o1D) + (size_t)(z & 3) * 256 * 256;
    float* o2 = (z < 4 ? o2S : o2D) + (size_t)(z & 3) * 128 * 128;
    float* o3 = (z < 4 ? o3S : o3D) + (size_t)(z & 3) * 64 * 64;

    const float w0 = 0.13533528323661270f;  // exp(-2)
    const float w1 = 0.60653065971263342f;  // exp(-0.5)
    const float wv[5] = {w0, w1, 1.0f, w1, w0};
    const float ksum = 1.0f + 2.0f * w1 + 2.0f * w0;
    const float norm = 1.0f / (ksum * ksum);

    // L0 halo: rows 64*by-14 .. +91, cols 64*bx-14 .. +91, zero outside image
    int Y0 = 64 * by - 14, X0 = 64 * bx - 14;
    for (int i = tid; i < 92 * 92; i += 256) {
        int r = i / 92, c = i - r * 92;
        int gy = Y0 + r, gx = X0 + c;
        l0[i] = (gy >= 0 && gy < 512 && gx >= 0 && gx < 512) ? in[(size_t)gy * 512 + gx] : 0.0f;
    }
    __syncthreads();

    // L1 patch 44x44 (global L1 rows 32*by-6 .. +43); zero outside L1 image
    for (int i = tid; i < 44 * 44; i += 256) {
        int r = i / 44, c = i - r * 44;
        int g1y = 32 * by - 6 + r, g1x = 32 * bx - 6 + c;
        float acc = 0.0f;
        if (g1y >= 0 && g1y < 256 && g1x >= 0 && g1x < 256) {
            #pragma unroll
            for (int py = 0; py < 2; py++) {
                #pragma unroll
                for (int px = 0; px < 2; px++) {
                    float s = 0.0f;
                    #pragma unroll
                    for (int a = 0; a < 5; a++)
                        #pragma unroll
                        for (int b = 0; b < 5; b++)
                            s += (wv[a] * wv[b] * norm) * l0[(2 * r + py + a) * 92 + (2 * c + px + b)];
                    acc += s;
                }
            }
            acc *= 0.25f;
        }
        l1[i] = acc;
        if (r >= 6 && r < 38 && c >= 6 && c < 38)
            o1[(size_t)(32 * by + r - 6) * 256 + (32 * bx + c - 6)] = acc;
    }
    __syncthreads();

    // L2 patch 20x20 (global L2 rows 16*by-2 .. +17)
    for (int i = tid; i < 400; i += 256) {
        int r = i / 20, c = i - r * 20;
        int g2y = 16 * by - 2 + r, g2x = 16 * bx - 2 + c;
        float acc = 0.0f;
        if (g2y >= 0 && g2y < 128 && g2x >= 0 && g2x < 128) {
            #pragma unroll
            for (int py = 0; py < 2; py++) {
                #pragma unroll
                for (int px = 0; px < 2; px++) {
                    float s = 0.0f;
                    #pragma unroll
                    for (int a = 0; a < 5; a++)
                        #pragma unroll
                        for (int b = 0; b < 5; b++)
                            s += (wv[a] * wv[b] * norm) * l1[(2 * r + py + a) * 44 + (2 * c + px + b)];
                    acc += s;
                }
            }
            acc *= 0.25f;
        }
        l2[i] = acc;
        if (r >= 2 && r < 18 && c >= 2 && c < 18)
            o2[(size_t)(16 * by + r - 2) * 128 + (16 * bx + c - 2)] = acc;
    }
    __syncthreads();

    // L3 8x8
    if (tid < 64) {
        int t = tid >> 3, u = tid & 7;
        float acc = 0.0f;
        #pragma unroll
        for (int py = 0; py < 2; py++) {
            #pragma unroll
            for (int px = 0; px < 2; px++) {
                float s = 0.0f;
                #pragma unroll
                for (int a = 0; a < 5; a++)
                    #pragma unroll
                    for (int b = 0; b < 5; b++)
                        s += (wv[a] * wv[b] * norm) * l2[(2 * t + py + a) * 20 + (2 * u + px + b)];
                acc += s;
            }
        }
        o3[(size_t)(8 * by + t) * 64 + (8 * bx + u)] = acc * 0.25f;
    }
}

// ---------------- block matching ----------------
__device__ __forceinline__ void bar_sync_128(int id) {
    asm volatile("bar.sync %0, %1;" :: "r"(id), "r"(128) : "memory");
}
__device__ __forceinline__ unsigned long long u64min(unsigned long long a, unsigned long long b) {
    return a < b ? a : b;
}

// Subpixel refine + result publish from the winning key. Run by one thread.
__device__ __forceinline__ void refine_store(
    const float* sdist, float inity, float initx, unsigned long long key, float* sres)
{
    int bk = (int)(key & 0xFFFFFFFFu);
    float best = __uint_as_float((unsigned)(key >> 32));
    int py = bk / 9, px = bk - py * 9;
    float offy = inity + (float)(py - SRR);
    float offx = initx + (float)(px - SRR);

    int fy = py + 1, fx = px + 1;
    float y00 = sdist[(fy - 1) * SSN + fx - 1], y01 = sdist[(fy - 1) * SSN + fx], y02 = sdist[(fy - 1) * SSN + fx + 1];
    float y10 = sdist[fy * SSN + fx - 1],       y11 = sdist[fy * SSN + fx],       y12 = sdist[fy * SSN + fx + 1];
    float y20 = sdist[(fy + 1) * SSN + fx - 1], y21 = sdist[(fy + 1) * SSN + fx], y22 = sdist[(fy + 1) * SSN + fx + 1];

    float a11 = (y00 - 2.f * y01 + y02 + 2.f * y10 - 4.f * y11 + 2.f * y12 + y20 - 2.f * y21 + y22) * 0.25f;
    a11 = fmaxf(a11, 0.0f);
    float a22 = (y00 + 2.f * y01 + y02 - 2.f * y10 - 4.f * y11 - 2.f * y12 + y20 + 2.f * y21 + y22) * 0.25f;
    a22 = fmaxf(a22, 0.0f);
    float a12 = (y00 - y02 - y20 + y22) * 0.25f;
    float b1  = (-y00 + y02 - 2.f * y10 + 2.f * y12 - y20 + y22) * 0.125f;
    float b2  = (-y00 - 2.f * y01 - y02 + y20 + 2.f * y21 + y22) * 0.125f;

    float det = a11 * a22 - a12 * a12;
    float a12z = (det < 0.0f) ? 0.0f : a12;
    float mu_x = -(a22 * b1 - a12z * b2) / det;
    float mu_y = -(a11 * b2 - a12z * b1) / det;
    float mu_len = sqrtf(mu_y * mu_y + mu_x * mu_x);
    if (mu_len < 1.0f) { offx += mu_x; offy += mu_y; }  // false for NaN/inf, as in JAX

    sres[0] = offy; sres[1] = offx; sres[2] = best;
}

// Child tile match on a 128-thread group (gl=0..127, unique barId).
// SSD arithmetic identical to the previously passing version.
__device__ __forceinline__ void tile_match_child(
    int ty, int tx, float inity, float initx,
    const float* __restrict__ dbase, int H, int W,
    int gl, int barId, float* swin, const float* stile, float* sdist,
    unsigned long long* spart, float* sres)
{
    int oy = (int)inity, ox = (int)initx;
    int y0 = ty * TSZ + oy - (SRR + PD);
    int x0 = tx * TSZ + ox - (SRR + PD);

    for (int i = gl; i < WINAREA; i += 128) {
        int wy = i / WINSZ, wx = i - wy * WINSZ;
        int gy = min(max(y0 + wy, 0), H - 1);
        int gx = min(max(x0 + wx, 0), W - 1);
        swin[i] = dbase[(size_t)gy * W + gx];
    }
    bar_sync_128(barId);

    if (gl < 96) {
        int cy = gl >> 3;
        int h = gl & 7;
        int cyc = (cy < SSN) ? cy : 0;

        float acc[SSN];
        #pragma unroll
        for (int c = 0; c < SSN; c++) acc[c] = 0.0f;

        #pragma unroll 1
        for (int rr = 0; rr < 2; rr++) {
            int yy = 2 * h + rr;
            const float* wr = swin + (cyc + yy) * WINSZ;
            float wreg[WINSZ];
            #pragma unroll
            for (int k = 0; k < WINSZ; k++) wreg[k] = wr[k];
            float treg[TSZ];
            const float4* t4 = (const float4*)(stile + yy * TSZ);
            #pragma unroll
            for (int q = 0; q < 4; q++) {
                float4 v = t4[q];
                treg[4 * q + 0] = v.x; treg[4 * q + 1] = v.y;
                treg[4 * q + 2] = v.z; treg[4 * q + 3] = v.w;
            }
            #pragma unroll
            for (int cx = 0; cx < SSN; cx++) {
                #pragma unroll
                for (int xx = 0; xx < TSZ; xx++) {
                    float d = wreg[cx + xx] - treg[xx];
                    acc[cx] = fmaf(d, d, acc[cx]);
                }
            }
        }
        #pragma unroll
        for (int c = 0; c < SSN; c++) {
            acc[c] += __shfl_down_sync(0xFFFFFFFFu, acc[c], 4);
            acc[c] += __shfl_down_sync(0xFFFFFFFFu, acc[c], 2);
            acc[c] += __shfl_down_sync(0xFFFFFFFFu, acc[c], 1);
        }
        if (h == 0 && cy < SSN) {
            float ay = (float)(cy - (SRR + PD)) / (float)SSN;
            #pragma unroll
            for (int cx = 0; cx < SSN; cx++) {
                float ax = (float)(cx - (SRR + PD)) / (float)SSN;
                sdist[cy * SSN + cx] = acc[cx] * (1.0f / 256.0f) + 0.1f * (ay * ay + ax * ax);
            }
        }
    }
    bar_sync_128(barId);

    // atomic-free argmin over cropped 9x9; first-occurrence tie-break via idx in low bits
    unsigned long long key = 0xFFFFFFFFFFFFFFFFull;
    if (gl < 81) {
        int py = gl / 9, px = gl - py * 9;
        float v = sdist[(py + 1) * SSN + (px + 1)];
        key = ((unsigned long long)__float_as_uint(v) << 32) | (unsigned)gl;
    }
    if (gl < 96) {
        #pragma unroll
        for (int o = 16; o >= 1; o >>= 1)
            key = u64min(key, __shfl_down_sync(0xFFFFFFFFu, key, o));
        if ((gl & 31) == 0) spart[gl >> 5] = key;
    }
    bar_sync_128(barId);

    if (gl == 0) {
        key = u64min(u64min(spart[0], spart[1]), spart[2]);
        refine_store(sdist, inity, initx, key, sres);
    }
    bar_sync_128(barId);
}

// Fused two-level match: one CTA = one parent tile + its 4 child tiles.
// Parent SSD now uses ALL 512 threads (thread = (cy, row-half), one warp per cy).
__global__ void __launch_bounds__(512) match2_kernel(
    const float* __restrict__ srcP, const float* __restrict__ dstP, int Hp, int Wp,
    const float* __restrict__ srcC, const float* __restrict__ dstC, int Hc, int Wc,
    const float* __restrict__ grandOff, int ntwg,
    float* __restrict__ outChildOff, int ntwc,
    float* __restrict__ outPixOff, float* __restrict__ outPixDist)
{
    __shared__ float s_win[4][WINAREA];
    __shared__ __align__(16) float s_tile[4][TSZ * TSZ];
    __shared__ __align__(16) float s_ptile[TSZ * TSZ];
    __shared__ float s_dist[4][SSN * SSN];
    __shared__ float s_pdist[SSN * SSN];
    __shared__ unsigned long long s_part[4][3];
    __shared__ unsigned long long s_ppart[3];
    __shared__ float s_res[4][3];
    __shared__ float s_pres[3];

    int tx = blockIdx.x, ty = blockIdx.y, n = blockIdx.z;
    int tid = threadIdx.x;
    const float* sPb = srcP + (size_t)n * Hp * Wp;
    const float* dPb = dstP + (size_t)n * Hp * Wp;
    const float* sCb = srcC + (size_t)n * Hc * Wc;
    const float* dCb = dstC + (size_t)n * Hc * Wc;

    // parent init offset: every thread reads the same address (broadcast) -- no barrier
    float inity = 0.0f, initx = 0.0f;
    if (grandOff) {
        const float* p = &grandOff[(((size_t)n * ntwg + (ty >> 1)) * ntwg + (tx >> 1)) * 2];
        float o0 = 2.0f * p[0], o1 = 2.0f * p[1];
        float fy = (float)(ty * TSZ), fx = (float)(tx * TSZ);
        inity = rintf(fminf(fmaxf(o0 + fy, 0.0f), (float)(Hp - TSZ)) - fy);
        initx = rintf(fminf(fmaxf(o1 + fx, 0.0f), (float)(Wp - TSZ)) - fx);
    }

    // ---- stage 0: all loads in parallel (parent window, parent tile, 4 child tiles) ----
    {
        int oy = (int)inity, ox = (int)initx;
        int y0 = ty * TSZ + oy - (SRR + PD);
        int x0 = tx * TSZ + ox - (SRR + PD);
        for (int i = tid; i < WINAREA; i += 512) {
            int wy = i / WINSZ, wx = i - wy * WINSZ;
            int gy = min(max(y0 + wy, 0), Hp - 1);
            int gx = min(max(x0 + wx, 0), Wp - 1);
            s_win[0][i] = dPb[(size_t)gy * Wp + gx];
        }
        if (tid < 256) {
            int yy = tid >> 4, xx = tid & 15;
            s_ptile[tid] = sPb[(size_t)(ty * TSZ + yy) * Wp + tx * TSZ + xx];
        }
        for (int i = tid; i < 4 * TSZ * TSZ; i += 512) {
            int child = i >> 8;
            int j = i & 255;
            int yy = j >> 4, xx = j & 15;
            int cty = 2 * ty + (child >> 1), ctx = 2 * tx + (child & 1);
            s_tile[child][j] = sCb[(size_t)(cty * TSZ + yy) * Wc + ctx * TSZ + xx];
        }
    }
    __syncthreads();

    // ---- stage 1: parent SSD across all 512 threads; warp w handles candidate row cy=w ----
    {
        int cyp = tid >> 5;        // warp index == candidate row
        int h = tid & 31;          // (row, half)
        if (cyp < SSN) {
            int row = h >> 1, half = h & 1;
            const float* wr = s_win[0] + (cyp + row) * WINSZ + half * 8;
            float wreg[18];
            #pragma unroll
            for (int k = 0; k < 18; k++) wreg[k] = wr[k];
            float treg[8];
            const float4* t4 = (const float4*)(s_ptile + row * TSZ + half * 8);
            float4 v0 = t4[0], v1 = t4[1];
            treg[0] = v0.x; treg[1] = v0.y; treg[2] = v0.z; treg[3] = v0.w;
            treg[4] = v1.x; treg[5] = v1.y; treg[6] = v1.z; treg[7] = v1.w;

            float acc[SSN];
            #pragma unroll
            for (int c = 0; c < SSN; c++) acc[c] = 0.0f;
            #pragma unroll
            for (int cx = 0; cx < SSN; cx++) {
                #pragma unroll
                for (int j = 0; j < 8; j++) {
                    float d = wreg[cx + j] - treg[j];
                    acc[cx] = fmaf(d, d, acc[cx]);
                }
            }
            #pragma unroll
            for (int c = 0; c < SSN; c++) {
                acc[c] += __shfl_down_sync(0xFFFFFFFFu, acc[c], 16);
                acc[c] += __shfl_down_sync(0xFFFFFFFFu, acc[c], 8);
                acc[c] += __shfl_down_sync(0xFFFFFFFFu, acc[c], 4);
                acc[c] += __shfl_down_sync(0xFFFFFFFFu, acc[c], 2);
                acc[c] += __shfl_down_sync(0xFFFFFFFFu, acc[c], 1);
            }
            if (h == 0) {
                float ay = (float)(cyp - (SRR + PD)) / (float)SSN;
                #pragma unroll
                for (int cx = 0; cx < SSN; cx++) {
                    float ax = (float)(cx - (SRR + PD)) / (float)SSN;
                    s_pdist[cyp * SSN + cx] = acc[cx] * (1.0f / 256.0f) + 0.1f * (ay * ay + ax * ax);
                }
            }
        }
    }
    __syncthreads();

    // parent argmin
    {
        unsigned long long key = 0xFFFFFFFFFFFFFFFFull;
        if (tid < 81) {
            int py = tid / 9, px = tid - py * 9;
            float v = s_pdist[(py + 1) * SSN + (px + 1)];
            key = ((unsigned long long)__float_as_uint(v) << 32) | (unsigned)tid;
        }
        if (tid < 96) {
            #pragma unroll
            for (int o = 16; o >= 1; o >>= 1)
                key = u64min(key, __shfl_down_sync(0xFFFFFFFFu, key, o));
            if ((tid & 31) == 0) s_ppart[tid >> 5] = key;
        }
    }
    __syncthreads();
    if (tid == 0) {
        unsigned long long key = u64min(u64min(s_ppart[0], s_ppart[1]), s_ppart[2]);
        refine_store(s_pdist, inity, initx, key, s_pres);
    }
    __syncthreads();

    // ---- stage 2: 4 children in parallel ----
    int group = tid >> 7, gl = tid & 127;
    int cty = 2 * ty + (group >> 1), ctx = 2 * tx + (group & 1);
    float o0 = 2.0f * s_pres[0], o1 = 2.0f * s_pres[1];
    float fy = (float)(cty * TSZ), fx = (float)(ctx * TSZ);
    float ciy = rintf(fminf(fmaxf(o0 + fy, 0.0f), (float)(Hc - TSZ)) - fy);
    float cix = rintf(fminf(fmaxf(o1 + fx, 0.0f), (float)(Wc - TSZ)) - fx);

    tile_match_child(cty, ctx, ciy, cix, dCb, Hc, Wc,
                     gl, /*barId=*/1 + group, s_win[group], s_tile[group], s_dist[group],
                     s_part[group], s_res[group]);

    if (outChildOff) {
        if (gl == 0) {
            float* o = &outChildOff[(((size_t)n * ntwc + cty) * ntwc + ctx) * 2];
            o[0] = s_res[group][0];
            o[1] = s_res[group][1];
        }
    }
    if (outPixOff) {
        float offy = s_res[group][0], offx = s_res[group][1], mind = s_res[group][2];
        float2* po = (float2*)outPixOff;
        float2 ov = make_float2(offy, offx);
        for (int i = gl; i < TSZ * TSZ; i += 128) {
            int yy = i >> 4, xx = i & 15;
            size_t pidx = ((size_t)n * Hc + cty * TSZ + yy) * Wc + ctx * TSZ + xx;
            po[pidx] = ov;
            outPixDist[pidx] = mind;
        }
    }
}

extern "C" void kernel_launch(void* const* d_in, const int* in_sizes, int n_in,
                              void* d_out, int out_size) {
    (void)in_sizes; (void)n_in; (void)out_size;
    const float* src = (const float*)d_in[0];
    const float* dst = (const float*)d_in[1];

    float *ps1, *ps2, *ps3, *pd1, *pd2, *pd3, *off2;
    cudaGetSymbolAddress((void**)&ps1, g_ps1);
    cudaGetSymbolAddress((void**)&ps2, g_ps2);
    cudaGetSymbolAddress((void**)&ps3, g_ps3);
    cudaGetSymbolAddress((void**)&pd1, g_pd1);
    cudaGetSymbolAddress((void**)&pd2, g_pd2);
    cudaGetSymbolAddress((void**)&pd3, g_pd3);
    cudaGetSymbolAddress((void**)&off2, g_off2);

    float* outPixOff = (float*)d_out;                              // (4,512,512,2)
    float* outPixDist = (float*)d_out + (size_t)4 * 512 * 512 * 2; // (4,512,512)

    // full pyramid in one launch
    blur_all_kernel<<<dim3(8, 8, 8), 256>>>(src, dst, ps1, pd1, ps2, pd2, ps3, pd3);

    // match: levels 3+2 fused, then levels 1+0 fused
    match2_kernel<<<dim3(4, 4, 4), 512>>>(ps3, pd3, 64, 64, ps2, pd2, 128, 128,
                                          nullptr, 0, off2, 8, nullptr, nullptr);
    match2_kernel<<<dim3(16, 16, 4), 512>>>(ps1, pd1, 256, 256, src, dst, 512, 512,
                                            off2, 8, nullptr, 0, outPixOff, outPixDist);
}